// round 2
// baseline (speedup 1.0000x reference)
#include <cuda_runtime.h>
#include <cuda_bf16.h>

#define N_NODES 100000
#define E_EDGES 1600000
#define DIN     256
#define DHID    64
#define DOUT    40
#define PROP_STEPS 16

// Scratch (allocation-free rule: __device__ globals)
__device__ float g_Y0[N_NODES * DHID];
__device__ float g_Y1[N_NODES * DHID];
__device__ float g_src[N_NODES * DHID];
__device__ int   g_row_ptr[N_NODES + 1];

// ---------------------------------------------------------------------------
// Kernel 1: CSR row pointers from sorted edge_row via per-thread lower_bound
// ---------------------------------------------------------------------------
__global__ void build_rowptr_kernel(const int* __restrict__ edge_row) {
    int r = blockIdx.x * blockDim.x + threadIdx.x;
    if (r > N_NODES) return;
    int lo = 0, hi = E_EDGES;
    while (lo < hi) {
        int mid = (lo + hi) >> 1;
        if (edge_row[mid] < r) lo = mid + 1; else hi = mid;
    }
    g_row_ptr[r] = lo;
}

// ---------------------------------------------------------------------------
// Kernel 2: h = x @ W1 + b1 ; Y0 = h ; src = 0.5 * diag * h
// Block tile 64 rows x 64 cols, 256 threads, 4x4 register tile, K-chunk 32.
// ---------------------------------------------------------------------------
__global__ __launch_bounds__(256) void gemm1_kernel(
    const float* __restrict__ x, const float* __restrict__ W1,
    const float* __restrict__ b1, const float* __restrict__ diag)
{
    __shared__ float xs[64][33];   // padded vs bank conflicts
    __shared__ float ws[32][64];

    const int tid = threadIdx.x;
    const int ty = tid >> 4;       // 0..15 -> row group
    const int tx = tid & 15;       // 0..15 -> col group
    const int row0 = blockIdx.x * 64;

    float acc[4][4];
    #pragma unroll
    for (int i = 0; i < 4; i++)
        #pragma unroll
        for (int j = 0; j < 4; j++) acc[i][j] = 0.f;

    for (int k0 = 0; k0 < DIN; k0 += 32) {
        // load x tile 64x32 (coalesced: consecutive tid -> consecutive k)
        #pragma unroll
        for (int i = 0; i < 8; i++) {
            int idx = tid + i * 256;
            int r = idx >> 5, kk = idx & 31;
            int gr = row0 + r;
            xs[r][kk] = (gr < N_NODES) ? x[gr * DIN + k0 + kk] : 0.f;
        }
        // load W1 tile 32x64 (coalesced over columns)
        #pragma unroll
        for (int i = 0; i < 8; i++) {
            int idx = tid + i * 256;
            int kk = idx >> 6, c = idx & 63;
            ws[kk][c] = W1[(k0 + kk) * DHID + c];
        }
        __syncthreads();

        #pragma unroll
        for (int kk = 0; kk < 32; kk++) {
            float a0 = xs[ty * 4 + 0][kk];
            float a1 = xs[ty * 4 + 1][kk];
            float a2 = xs[ty * 4 + 2][kk];
            float a3 = xs[ty * 4 + 3][kk];
            float w0 = ws[kk][tx * 4 + 0];
            float w1 = ws[kk][tx * 4 + 1];
            float w2 = ws[kk][tx * 4 + 2];
            float w3 = ws[kk][tx * 4 + 3];
            acc[0][0] += a0 * w0; acc[0][1] += a0 * w1; acc[0][2] += a0 * w2; acc[0][3] += a0 * w3;
            acc[1][0] += a1 * w0; acc[1][1] += a1 * w1; acc[1][2] += a1 * w2; acc[1][3] += a1 * w3;
            acc[2][0] += a2 * w0; acc[2][1] += a2 * w1; acc[2][2] += a2 * w2; acc[2][3] += a2 * w3;
            acc[3][0] += a3 * w0; acc[3][1] += a3 * w1; acc[3][2] += a3 * w2; acc[3][3] += a3 * w3;
        }
        __syncthreads();
    }

    #pragma unroll
    for (int i = 0; i < 4; i++) {
        int gr = row0 + ty * 4 + i;
        if (gr < N_NODES) {
            float dv = 0.5f * diag[gr];
            #pragma unroll
            for (int j = 0; j < 4; j++) {
                int c = tx * 4 + j;
                float h = acc[i][j] + b1[c];
                g_Y0[gr * DHID + c] = h;
                g_src[gr * DHID + c] = dv * h;
            }
        }
    }
}

// ---------------------------------------------------------------------------
// Kernel 3: one propagation step. One warp per row; lane owns 2 columns.
// Yout[r] = 0.5*(Yin[r] + sum_e val_e * Yin[col_e]) + src[r]
// ---------------------------------------------------------------------------
__global__ __launch_bounds__(256) void prop_kernel(
    const int* __restrict__ ecol, const float* __restrict__ evalv, int phase)
{
    const float* __restrict__ Yin  = phase ? g_Y1 : g_Y0;
    float*       __restrict__ Yout = phase ? g_Y0 : g_Y1;

    int w = (blockIdx.x * blockDim.x + threadIdx.x) >> 5;
    if (w >= N_NODES) return;
    int lane = threadIdx.x & 31;

    int e   = g_row_ptr[w];
    int end = g_row_ptr[w + 1];

    float ax = 0.f, ay = 0.f;

    // 4-edge unroll: exposes 4 independent L2 gathers for MLP
    for (; e + 4 <= end; e += 4) {
        int   c0 = ecol[e],     c1 = ecol[e + 1], c2 = ecol[e + 2], c3 = ecol[e + 3];
        float v0 = evalv[e],    v1 = evalv[e + 1], v2 = evalv[e + 2], v3 = evalv[e + 3];
        float2 y0 = *(const float2*)&Yin[c0 * DHID + lane * 2];
        float2 y1 = *(const float2*)&Yin[c1 * DHID + lane * 2];
        float2 y2 = *(const float2*)&Yin[c2 * DHID + lane * 2];
        float2 y3 = *(const float2*)&Yin[c3 * DHID + lane * 2];
        ax += v0 * y0.x + v1 * y1.x + v2 * y2.x + v3 * y3.x;
        ay += v0 * y0.y + v1 * y1.y + v2 * y2.y + v3 * y3.y;
    }
    for (; e < end; e++) {
        int   c = ecol[e];
        float v = evalv[e];
        float2 y = *(const float2*)&Yin[c * DHID + lane * 2];
        ax += v * y.x;
        ay += v * y.y;
    }

    float2 yr = *(const float2*)&Yin[w * DHID + lane * 2];
    float2 s  = *(const float2*)&g_src[w * DHID + lane * 2];
    float2 o;
    o.x = 0.5f * (yr.x + ax) + s.x;
    o.y = 0.5f * (yr.y + ay) + s.y;
    *(float2*)&Yout[w * DHID + lane * 2] = o;
}

// ---------------------------------------------------------------------------
// Kernel 4: out = relu(Y) @ W2 + b2.  64-row tile per block, W2/Y in smem.
// ---------------------------------------------------------------------------
__global__ __launch_bounds__(256) void mlp2_kernel(
    const float* __restrict__ W2, const float* __restrict__ b2,
    float* __restrict__ out)
{
    __shared__ float w2s[64][41];
    __shared__ float ys[64][65];
    __shared__ float b2s[DOUT];

    const int tid = threadIdx.x;
    const int row0 = blockIdx.x * 64;

    for (int idx = tid; idx < DHID * DOUT; idx += 256)
        w2s[idx / DOUT][idx % DOUT] = W2[idx];
    if (tid < DOUT) b2s[tid] = b2[tid];

    #pragma unroll
    for (int i = 0; i < 16; i++) {
        int idx = tid + i * 256;     // 4096 = 64*64
        int r = idx >> 6, c = idx & 63;
        int gr = row0 + r;
        ys[r][c] = (gr < N_NODES) ? fmaxf(g_Y0[gr * DHID + c], 0.f) : 0.f;
    }
    __syncthreads();

    const int row = tid >> 2;    // 0..63
    const int cg  = tid & 3;     // 0..3 -> 10 cols each
    float acc[10];
    #pragma unroll
    for (int i = 0; i < 10; i++) acc[i] = b2s[cg * 10 + i];

    #pragma unroll 8
    for (int j = 0; j < DHID; j++) {
        float yv = ys[row][j];
        #pragma unroll
        for (int i = 0; i < 10; i++)
            acc[i] += yv * w2s[j][cg * 10 + i];
    }

    int gr = row0 + row;
    if (gr < N_NODES) {
        #pragma unroll
        for (int i = 0; i < 10; i++)
            out[gr * DOUT + cg * 10 + i] = acc[i];
    }
}

// ---------------------------------------------------------------------------
extern "C" void kernel_launch(void* const* d_in, const int* in_sizes, int n_in,
                              void* d_out, int out_size)
{
    const float* x     = (const float*)d_in[0];
    const int*   erow  = (const int*)  d_in[1];
    const int*   ecol  = (const int*)  d_in[2];
    const float* evalv = (const float*)d_in[3];
    const float* diag  = (const float*)d_in[4];
    const float* W1    = (const float*)d_in[5];
    const float* b1    = (const float*)d_in[6];
    const float* W2    = (const float*)d_in[7];
    const float* b2    = (const float*)d_in[8];
    float* out = (float*)d_out;

    build_rowptr_kernel<<<(N_NODES + 1 + 255) / 256, 256>>>(erow);

    int gemm_blocks = (N_NODES + 63) / 64;
    gemm1_kernel<<<gemm_blocks, 256>>>(x, W1, b1, diag);

    int prop_blocks = (N_NODES * 32 + 255) / 256;   // one warp per row
    for (int s = 0; s < PROP_STEPS; s++) {
        // step s reads phase (s&1): Y0 first, then ping-pong; 16 steps end in Y0
        prop_kernel<<<prop_blocks, 256>>>(ecol, evalv, s & 1);
    }

    mlp2_kernel<<<gemm_blocks, 256>>>(W2, b2, out);
}